// round 4
// baseline (speedup 1.0000x reference)
#include <cuda_runtime.h>

// Problem constants (fixed by reference)
#define N_TOK 16384
#define DIM   1024
#define NPATH 8
#define CAP   4096
#define TPB   256
#define NBLK  (N_TOK / TPB)   // 64

// Scratch (allocation-free: __device__ globals)
__device__ int   g_path[N_TOK];
__device__ float g_gate[N_TOK];
__device__ int   g_blockCount[NBLK * NPATH];
__device__ int   g_blockOffset[NBLK * NPATH];
__device__ int   g_count[NPATH];          // clamped to CAP
__device__ int   g_inv[NPATH * CAP];      // token index for (path, slot)

// ---------------------------------------------------------------------------
// Kernel 1: per-token argmax + per-block path histogram.
// jnp.argmax keeps the FIRST max -> strict '>' comparison.
// ---------------------------------------------------------------------------
__global__ void __launch_bounds__(TPB)
route_kernel(const float* __restrict__ scores) {
    int i = blockIdx.x * TPB + threadIdx.x;
    __shared__ int cnt[NPATH];
    if (threadIdx.x < NPATH) cnt[threadIdx.x] = 0;
    __syncthreads();

    const float4* s4 = reinterpret_cast<const float4*>(scores);
    float4 a = s4[i * 2 + 0];
    float4 b = s4[i * 2 + 1];
    float v[8] = {a.x, a.y, a.z, a.w, b.x, b.y, b.z, b.w};
    int best = 0;
    float bv = v[0];
#pragma unroll
    for (int k = 1; k < 8; k++) {
        if (v[k] > bv) { bv = v[k]; best = k; }
    }
    g_path[i] = best;
    g_gate[i] = bv;
    atomicAdd(&cnt[best], 1);          // order-independent sum -> deterministic
    __syncthreads();
    if (threadIdx.x < NPATH)
        g_blockCount[blockIdx.x * NPATH + threadIdx.x] = cnt[threadIdx.x];
}

// ---------------------------------------------------------------------------
// Kernel 2: exclusive scan of block counts per path (tiny: 8 x 64).
// Launched as one full warp; lanes 8..31 idle.
// ---------------------------------------------------------------------------
__global__ void scan_kernel() {
    int p = threadIdx.x;
    if (p >= NPATH) return;
    int run = 0;
#pragma unroll 8
    for (int b = 0; b < NBLK; b++) {
        g_blockOffset[b * NPATH + p] = run;
        run += g_blockCount[b * NPATH + p];
    }
    g_count[p] = run < CAP ? run : CAP;
}

// ---------------------------------------------------------------------------
// Kernel 3: stable global slot per token; build inverse map inv[p][slot]=tok.
// Warp rank via __match_any_sync, then scan warp counts in shared memory.
// ---------------------------------------------------------------------------
__global__ void __launch_bounds__(TPB)
slot_kernel() {
    int i    = blockIdx.x * TPB + threadIdx.x;
    int p    = g_path[i];
    int warp = threadIdx.x >> 5;
    int lane = threadIdx.x & 31;

    unsigned m     = __match_any_sync(0xffffffffu, p);
    int      wrank = __popc(m & ((1u << lane) - 1u));

    __shared__ int wcnt[8][NPATH];     // 8 warps x 8 paths
    if (threadIdx.x < 8 * NPATH)
        reinterpret_cast<int*>(wcnt)[threadIdx.x] = 0;
    __syncthreads();
    if (wrank == 0) wcnt[warp][p] = __popc(m);   // leader = lowest matching lane
    __syncthreads();

    int base = g_blockOffset[blockIdx.x * NPATH + p];
#pragma unroll
    for (int w = 0; w < 8; w++)
        if (w < warp) base += wcnt[w][p];

    int slot = base + wrank;
    if (slot < CAP) g_inv[p * CAP + slot] = i;   // overflow tokens dropped
}

// ---------------------------------------------------------------------------
// Kernel 4 (heavy): one block per output row (p, r). 256 threads x float4
// covers the 1024-float row. Copies x[tok]*gate or zeros. Output written once
// (198 MB total traffic -> HBM-bound floor ~33 us).
// ---------------------------------------------------------------------------
__global__ void __launch_bounds__(TPB)
fill_kernel(const float* __restrict__ x, float* __restrict__ out) {
    int row = blockIdx.x;             // row = p * CAP + r, CAP = 4096
    int p   = row >> 12;
    int r   = row & (CAP - 1);
    int t   = threadIdx.x;            // 0..255 -> float4 index within row

    float4* o4 = reinterpret_cast<float4*>(out) + (size_t)row * (DIM / 4);

    int cnt = __ldg(&g_count[p]);
    if (r < cnt) {
        int   tok = __ldg(&g_inv[row]);
        float g   = __ldg(&g_gate[tok]);
        const float4* x4 =
            reinterpret_cast<const float4*>(x) + (size_t)tok * (DIM / 4);
        float4 v = __ldg(&x4[t]);
        o4[t] = make_float4(v.x * g, v.y * g, v.z * g, v.w * g);
    } else {
        o4[t] = make_float4(0.f, 0.f, 0.f, 0.f);
    }
}

// ---------------------------------------------------------------------------
// Launch
// ---------------------------------------------------------------------------
extern "C" void kernel_launch(void* const* d_in, const int* in_sizes, int n_in,
                              void* d_out, int out_size) {
    const float* x      = (const float*)d_in[0];   // [16384, 1024]
    const float* scores = (const float*)d_in[1];   // [16384, 8]
    float*       out    = (float*)d_out;           // [8, 4096, 1024]

    route_kernel<<<NBLK, TPB>>>(scores);
    scan_kernel<<<1, 32>>>();
    slot_kernel<<<NBLK, TPB>>>();
    fill_kernel<<<NPATH * CAP, TPB>>>(x, out);
}

// round 5
// speedup vs baseline: 1.2521x; 1.2521x over previous
#include <cuda_runtime.h>

// Problem constants (fixed by reference)
#define N_TOK 16384
#define DIM   1024
#define NPATH 8
#define CAP   4096
#define TPB   256
#define NBLK  (N_TOK / TPB)   // 64
#define G     4               // rows per fill block

// Scratch (allocation-free: __device__ globals)
__device__ float    g_gate[N_TOK];
__device__ int      g_blockCount[NBLK * NPATH];
__device__ int      g_count[NPATH];          // clamped to CAP
__device__ int      g_inv[NPATH * CAP];      // token index for (path, slot)
__device__ unsigned g_bar;                   // arrival counter (never reset; epoch trick)

// ---------------------------------------------------------------------------
// Fused prologue: argmax route + per-block histogram + grid barrier +
// redundant per-block scan + stable slot assignment. 64 blocks x 256 thr,
// all co-resident on 148 SMs -> spin barrier is deadlock-free.
// Replay-safe: each launch adds exactly NBLK arrivals; epoch = ticket/NBLK.
// ---------------------------------------------------------------------------
__global__ void __launch_bounds__(TPB)
prologue_kernel(const float* __restrict__ scores) {
    int b   = blockIdx.x;
    int tid = threadIdx.x;
    int i   = b * TPB + tid;

    __shared__ int cnt[NPATH];
    __shared__ int s_off[NPATH];
    if (tid < NPATH) cnt[tid] = 0;
    __syncthreads();

    // --- Phase 1: argmax (first-max wins, matches jnp.argmax) + histogram ---
    const float4* s4 = reinterpret_cast<const float4*>(scores);
    float4 a = s4[i * 2 + 0];
    float4 c = s4[i * 2 + 1];
    float v[8] = {a.x, a.y, a.z, a.w, c.x, c.y, c.z, c.w};
    int best = 0;
    float bv = v[0];
#pragma unroll
    for (int k = 1; k < 8; k++)
        if (v[k] > bv) { bv = v[k]; best = k; }

    g_gate[i] = bv;
    atomicAdd(&cnt[best], 1);
    __syncthreads();
    if (tid < NPATH) g_blockCount[b * NPATH + tid] = cnt[tid];
    __threadfence();
    __syncthreads();

    // --- Grid arrival barrier (monotonic counter, epoch-based target) ---
    if (tid == 0) {
        unsigned ticket = atomicAdd(&g_bar, 1u);
        unsigned target = ((ticket / NBLK) + 1u) * NBLK;
        while (atomicAdd(&g_bar, 0u) < target) { }
    }
    __syncthreads();
    __threadfence();   // acquire: counts from all blocks now visible

    // --- Phase 2: redundant scan of block counts for this block's offsets ---
    if (tid < NPATH) {
        int off = 0, total = 0;
#pragma unroll 8
        for (int bb = 0; bb < NBLK; bb++) {
            int cc = g_blockCount[bb * NPATH + tid];
            if (bb < b) off += cc;
            total += cc;
        }
        s_off[tid] = off;
        if (b == 0) g_count[tid] = total < CAP ? total : CAP;
    }
    __syncthreads();

    // --- Phase 3: stable intra-block rank via match_any + warp-count scan ---
    int warp = tid >> 5;
    int lane = tid & 31;
    unsigned m     = __match_any_sync(0xffffffffu, best);
    int      wrank = __popc(m & ((1u << lane) - 1u));

    __shared__ int wcnt[8][NPATH];
    if (tid < 8 * NPATH) reinterpret_cast<int*>(wcnt)[tid] = 0;
    __syncthreads();
    if (wrank == 0) wcnt[warp][best] = __popc(m);
    __syncthreads();

    int base = s_off[best];
#pragma unroll
    for (int w = 0; w < 8; w++)
        if (w < warp) base += wcnt[w][best];

    int slot = base + wrank;
    if (slot < CAP) g_inv[best * CAP + slot] = i;   // overflow tokens dropped
}

// ---------------------------------------------------------------------------
// Fill: G=4 rows per block (8192 blocks x 256 thr). Batched index/gate/data
// loads -> 4 independent memory chains per thread. Streaming stores keep
// x resident in L2 across replays. Output written exactly once.
// ---------------------------------------------------------------------------
__global__ void __launch_bounds__(TPB)
fill_kernel(const float* __restrict__ x, float* __restrict__ out) {
    int row0 = blockIdx.x * G;        // G=4 divides CAP -> group never crosses a path
    int p    = row0 >> 12;
    int t    = threadIdx.x;           // float4 index within row (0..255)

    int cnt = __ldg(&g_count[p]);

    bool act[G];
    int  tok[G];
#pragma unroll
    for (int j = 0; j < G; j++) {
        int row = row0 + j;
        act[j] = (row & (CAP - 1)) < cnt;
        tok[j] = act[j] ? __ldg(&g_inv[row]) : 0;
    }

    float gt[G];
#pragma unroll
    for (int j = 0; j < G; j++)
        gt[j] = act[j] ? __ldg(&g_gate[tok[j]]) : 0.0f;

    float4 v[G];
#pragma unroll
    for (int j = 0; j < G; j++) {
        if (act[j]) {
            const float4* x4 =
                reinterpret_cast<const float4*>(x) + (size_t)tok[j] * (DIM / 4);
            float4 w = __ldg(&x4[t]);
            v[j] = make_float4(w.x * gt[j], w.y * gt[j], w.z * gt[j], w.w * gt[j]);
        } else {
            v[j] = make_float4(0.f, 0.f, 0.f, 0.f);
        }
    }

#pragma unroll
    for (int j = 0; j < G; j++) {
        float4* o4 = reinterpret_cast<float4*>(out) +
                     (size_t)(row0 + j) * (DIM / 4) + t;
        __stcs(o4, v[j]);             // evict-first: don't thrash L2 (x lives there)
    }
}

// ---------------------------------------------------------------------------
// Launch
// ---------------------------------------------------------------------------
extern "C" void kernel_launch(void* const* d_in, const int* in_sizes, int n_in,
                              void* d_out, int out_size) {
    const float* x      = (const float*)d_in[0];   // [16384, 1024]
    const float* scores = (const float*)d_in[1];   // [16384, 8]
    float*       out    = (float*)d_out;           // [8, 4096, 1024]

    prologue_kernel<<<NBLK, TPB>>>(scores);
    fill_kernel<<<NPATH * CAP / G, TPB>>>(x, out);
}